// round 7
// baseline (speedup 1.0000x reference)
#include <cuda_runtime.h>
#include <cstdint>
#include <cstddef>

// ---------------------------------------------------------------------------
// WaveNet gated residual block, single fused kernel, tf32 mma.sync (sm_103
// baseline PTX — tcgen05 unavailable under compute_103).
//
// Per CTA (128-token tile, 16 warps):
//   - x tile (128 rows + 4 halo) loaded ONCE into smem (paired layout),
//     placed in the m-region's q128..255 half.
//   - gate pass p=0,1 : acc[128,256] = A x Wg(p)^T, A read from resident x
//     (tap0 = rows r-4, tap1 = rows r); epilogue m = tanh*sig -> m region
//     (pass 0 -> q0..127, pass 1 -> q128..255, overwriting x after use).
//   - out pass0 [128,256] = m x Wo[res|skip0]^T ; out pass1 [128,128] skip1.
//   - B (weights) streamed in 32-KB chunks through a 3-stage cp.async ring,
//     ONE __syncthreads per chunk.
//
// m/x paired layout: float4 slot = [r:(k,k+4), r+8:(k,k+4)]; slot address
// S(row,j) = ((row>>4)*32 + (j>>2))*32 + (row&7)*4 + (j&3)  (float4 units)
// -> LDS.128 fragment loads conflict-free across the warp.
// ---------------------------------------------------------------------------

#define DEVFN __device__ __forceinline__

static constexpr int XHALO = 32768;            // float offset of 4-row halo
static constexpr int BOFF  = 33280;            // float offset of B ring
static constexpr int SMEM_BYTES = (33280 + 3 * 8192) * 4;   // 231424

__device__ float wscratch[896 * 256];          // packed tf32 weights (896 KB)
__device__ float xscratch[131072 * 128];       // tf32-rounded, q-packed x (64 MB)

// ------------------------------- helpers -----------------------------------
DEVFN uint32_t smaddr(const void* p) {
    uint32_t a;
    asm("{ .reg .u64 t; cvta.to.shared.u64 t, %1; cvt.u32.u64 %0, t; }" : "=r"(a) : "l"(p));
    return a;
}
DEVFN uint32_t tf32r(float x) { uint32_t u; asm("cvt.rna.tf32.f32 %0, %1;" : "=r"(u) : "f"(x)); return u; }
DEVFN float ex2f(float x) { float y; asm("ex2.approx.ftz.f32 %0, %1;" : "=f"(y) : "f"(x)); return y; }
DEVFN float rcpf(float x) { float y; asm("rcp.approx.ftz.f32 %0, %1;" : "=f"(y) : "f"(x)); return y; }

// gated activation: tanh(a)*sigmoid(b) = (u-1)*v / ((u+1)*(v+1)),
// u = e^{2a}, v = e^{b}; clamped (saturation-safe), tf32-rounded.
DEVFN float gatem(float a, float b) {
    a = fminf(fmaxf(a, -15.f), 15.f);
    b = fminf(fmaxf(b, -30.f), 30.f);
    float u = ex2f(a * 2.8853900817779268f);
    float v = ex2f(b * 1.4426950408889634f);
    float m = (u - 1.f) * v * rcpf((u + 1.f) * (v + 1.f));
    return __uint_as_float(tf32r(m));
}

DEVFN void cpa16(uint32_t dst, const void* src, int sz) {
    asm volatile("cp.async.cg.shared.global [%0], [%1], 16, %2;"
                 :: "r"(dst), "l"(src), "r"(sz) : "memory");
}
DEVFN void cpa8(uint32_t dst, const void* src) {
    asm volatile("cp.async.ca.shared.global [%0], [%1], 8;"
                 :: "r"(dst), "l"(src) : "memory");
}
DEVFN void cpcommit() { asm volatile("cp.async.commit_group;" ::: "memory"); }
#define CPWAIT(n) asm volatile("cp.async.wait_group %0;" :: "n"(n) : "memory")

// m16n8k8 tf32 mma, row.col, f32 accum
DEVFN void mma8(float* d, const uint32_t* a, const uint32_t* b) {
    asm("mma.sync.aligned.m16n8k8.row.col.f32.tf32.tf32.f32 "
        "{%0,%1,%2,%3}, {%4,%5,%6,%7}, {%8,%9}, {%0,%1,%2,%3};"
        : "+f"(d[0]), "+f"(d[1]), "+f"(d[2]), "+f"(d[3])
        : "r"(a[0]), "r"(a[1]), "r"(a[2]), "r"(a[3]), "r"(b[0]), "r"(b[1]));
}

// ------------------------------ prep kernel --------------------------------
// wscratch rows (each 256 q-packed floats, q(k)=(k&~7)+((k&3)<<1)+((k>>2)&1)):
//   0..511   gate: row = p*256 + t; G=t>>4, is_sig=(t>>3)&1, e=t&7,
//            channel C = p*128 + G*8 + (e>>1) + (e&1)*4  (pairing permutation)
//   512..767 out0: res 0..127 | skip 0..127
//   768..895 out1: skip 128..255
// xscratch: 128 q-packed tf32 floats per token.
__global__ void __launch_bounds__(256)
prep_kernel(const float* __restrict__ wt, const float* __restrict__ ws,
            const float* __restrict__ wr, const float* __restrict__ wk,
            const float* __restrict__ x) {
    int bid = blockIdx.x, tid = threadIdx.x;
    if (bid < 896) {
        int idx = bid * 256 + tid;
        int row = idx >> 8, k = idx & 255;
        float v;
        if (row < 512) {
            int p = row >> 8, t = row & 255;
            int G = t >> 4, is_sig = (t >> 3) & 1, e = t & 7;
            int C = p * 128 + G * 8 + (e >> 1) + (e & 1) * 4;
            int src = ((k >> 7) * 128 + (k & 127)) * 256 + C;
            v = is_sig ? ws[src] : wt[src];
        } else if (row < 768) {
            int j = row - 512;
            v = (j < 128) ? wr[k * 128 + j] : wk[k * 256 + (j - 128)];
        } else {
            v = wk[k * 256 + 128 + (row - 768)];
        }
        int q = (k & ~7) + ((k & 3) << 1) + ((k >> 2) & 1);
        wscratch[row * 256 + q] = __uint_as_float(tf32r(v));
    } else {
        size_t g = (size_t)(bid - 896) * 256 + tid;   // < 2097152
        const float* src = x + g * 8;
        float4 lo = *(const float4*)src;
        float4 hi = *(const float4*)(src + 4);
        float4 o0 = make_float4(__uint_as_float(tf32r(lo.x)), __uint_as_float(tf32r(hi.x)),
                                __uint_as_float(tf32r(lo.y)), __uint_as_float(tf32r(hi.y)));
        float4 o1 = make_float4(__uint_as_float(tf32r(lo.z)), __uint_as_float(tf32r(hi.z)),
                                __uint_as_float(tf32r(lo.w)), __uint_as_float(tf32r(hi.w)));
        float* dst = xscratch + g * 8;
        *(float4*)dst = o0;
        *(float4*)(dst + 4) = o1;
    }
}

// ------------------------------ fused kernel -------------------------------
__global__ void __launch_bounds__(512, 1)
fused_kernel(const float* __restrict__ x,
             const float* __restrict__ bt, const float* __restrict__ bs,
             const float* __restrict__ br, const float* __restrict__ bk,
             float* __restrict__ out) {
    extern __shared__ float sm[];
    uint32_t sb = smaddr(sm);
    int tid = threadIdx.x, wid = tid >> 5, lid = tid & 31;
    int r0 = lid >> 2, c0 = lid & 3;
    int rx3 = r0 & 3;
    int mw = wid >> 3, nw = wid & 7;        // 2M x 8N (gate / out0)
    int mw4 = wid >> 2, nw4 = wid & 3;      // 4M x 4N (out1)
    int tile = blockIdx.x;
    long g0 = (long)tile * 128;
    bool head = (tile & 127) == 0;          // first tile in a batch row

    float acc[4][4][4];

    // per-thread B-loader constants
    const int ldb = tid & 7, ldrow = tid >> 3;
    const uint32_t ldswz = 4u * (uint32_t)(ldb ^ ((ldrow & 3) << 1));

    // stream weight chunk ci (pass=ci>>3, kc=ci&7) into ring stage ci%3
    auto loadChunk = [&](int ci) {
        int pass = ci >> 3, kc = ci & 7, st = ci % 3;
        const float* src = wscratch + pass * 65536 + ldrow * 256 + kc * 32 + ldb * 4;
        uint32_t dst = sb + (uint32_t)(BOFF + st * 8192 + ldrow * 32) * 4 + ldswz * 4;
        int iters = (pass == 3) ? 2 : 4;
        for (int i = 0; i < iters; ++i)
            cpa16(dst + (uint32_t)i * 64 * 32 * 4, src + i * 64 * 256, 16);
    };

    // x tile -> resident paired layout at j-blocks 16..31 (q128..255)
    auto loadX = [&]() {
        int rown = tid >> 2, quad = tid & 3;
        const float* src = xscratch + (g0 + rown) * 128 + quad * 2;
        uint32_t dbase = sb + (uint32_t)(((rown >> 4) * 32 + 16) * 128 + (rown & 7) * 16
                                         + quad * 4 + ((rown >> 3) & 1) * 2) * 4;
#pragma unroll
        for (int jj = 0; jj < 16; ++jj)
            cpa8(dbase + (uint32_t)jj * 512, src + jj * 8);
    };
    auto loadHalo = [&]() {
        if (tid < 128) {
            int hr = tid >> 5, gq = tid & 31;
            const float* src = head ? xscratch : (xscratch + (g0 - 4 + hr) * 128 + gq * 4);
            cpa16(sb + (uint32_t)(XHALO + hr * 128 + gq * 4) * 4, src, head ? 0 : 16);
        }
    };

    auto zacc = [&]() {
#pragma unroll
        for (int i = 0; i < 4; ++i)
#pragma unroll
            for (int j = 0; j < 4; ++j)
#pragma unroll
                for (int q = 0; q < 4; ++q) acc[i][j][q] = 0.f;
    };

    // ---- compute: A(paired LDS.128 from m/x region) x B(stage), 256 N rows ----
    auto mm256 = [&](int st, int kc) {
        const float* Ax = sm + (mw * 128 + kc * 4) * 128 + r0 * 16 + c0 * 4;
        const float* Bs = sm + BOFF + st * 8192 + nw * 1024 + r0 * 32;
#pragma unroll
        for (int ks = 0; ks < 4; ++ks) {
            int o = ((ks ^ rx3) << 3) + 2 * c0;
            uint32_t a[4][4];
#pragma unroll
            for (int mf = 0; mf < 4; ++mf) {
                float4 f = *(const float4*)(Ax + mf * 4096 + ks * 128);
                a[mf][0] = __float_as_uint(f.x); a[mf][1] = __float_as_uint(f.z);
                a[mf][2] = __float_as_uint(f.y); a[mf][3] = __float_as_uint(f.w);
            }
#pragma unroll
            for (int nf = 0; nf < 4; ++nf) {
                float2 bv = *(const float2*)(Bs + nf * 256 + o);
                uint32_t b[2] = {__float_as_uint(bv.x), __float_as_uint(bv.y)};
#pragma unroll
                for (int mf = 0; mf < 4; ++mf) mma8(acc[mf][nf], a[mf], b);
            }
        }
    };

    // ---- gate tap0 (k<128): A rows (r-4, r+4) from resident x (+halo) ----
    auto mm256_t0 = [&](int st, int kc) {
        const float* Bs = sm + BOFF + st * 8192 + nw * 1024 + r0 * 32;
        int jb = 16 + kc * 4;
        const float* baseHi = sm + (mw * 128 + jb) * 128 + ((r0 + 4) & 7) * 16 + c0 * 4
                              + ((r0 >= 4) ? 2 : 0);
        const float* baseLo = (r0 >= 4)
            ? sm + (mw * 128 + jb) * 128 + (r0 - 4) * 16 + c0 * 4
            : sm + (mw * 128 - 32 + jb) * 128 + (r0 + 4) * 16 + c0 * 4 + 2;
        const float* haloB = sm + XHALO + r0 * 128 + kc * 32 + 2 * c0;
        bool useHalo = (mw == 0) && (r0 < 4);
#pragma unroll
        for (int ks = 0; ks < 4; ++ks) {
            int o = ((ks ^ rx3) << 3) + 2 * c0;
            uint32_t a[4][4];
#pragma unroll
            for (int mf = 0; mf < 4; ++mf) {
                const float* plo = (useHalo && mf == 0) ? (haloB + ks * 8)
                                                        : (baseLo + mf * 4096 + ks * 128);
                float2 lo = *(const float2*)plo;
                float2 hi = *(const float2*)(baseHi + mf * 4096 + ks * 128);
                a[mf][0] = __float_as_uint(lo.x); a[mf][1] = __float_as_uint(hi.x);
                a[mf][2] = __float_as_uint(lo.y); a[mf][3] = __float_as_uint(hi.y);
            }
#pragma unroll
            for (int nf = 0; nf < 4; ++nf) {
                float2 bv = *(const float2*)(Bs + nf * 256 + o);
                uint32_t b[2] = {__float_as_uint(bv.x), __float_as_uint(bv.y)};
#pragma unroll
                for (int mf = 0; mf < 4; ++mf) mma8(acc[mf][nf], a[mf], b);
            }
        }
    };

    // ---- out1: 4M x 4N, A rows 32*mw4 + 16mf + r0, B 128 rows ----
    auto mm128 = [&](int st, int kc) {
        const float* Ax = sm + (mw4 * 64 + kc * 4) * 128 + r0 * 16 + c0 * 4;
        const float* Bs = sm + BOFF + st * 8192 + nw4 * 1024 + r0 * 32;
#pragma unroll
        for (int ks = 0; ks < 4; ++ks) {
            int o = ((ks ^ rx3) << 3) + 2 * c0;
            uint32_t a[2][4];
#pragma unroll
            for (int mf = 0; mf < 2; ++mf) {
                float4 f = *(const float4*)(Ax + mf * 4096 + ks * 128);
                a[mf][0] = __float_as_uint(f.x); a[mf][1] = __float_as_uint(f.z);
                a[mf][2] = __float_as_uint(f.y); a[mf][3] = __float_as_uint(f.w);
            }
#pragma unroll
            for (int nf = 0; nf < 4; ++nf) {
                float2 bv = *(const float2*)(Bs + nf * 256 + o);
                uint32_t b[2] = {__float_as_uint(bv.x), __float_as_uint(bv.y)};
#pragma unroll
                for (int mf = 0; mf < 2; ++mf) mma8(acc[mf][nf], a[mf], b);
            }
        }
    };

    // ---- gate epilogue: one STS.128 per fragment pair ----
    auto gate_epi = [&](int p) {
        int Sb = mw * 4096 + p * 512 + r0 * 4 + c0;
#pragma unroll
        for (int mf = 0; mf < 4; ++mf)
#pragma unroll
            for (int gs = 0; gs < 2; ++gs) {
                int G = nw * 2 + gs;
                int Cb = p * 128 + G * 8;
                float bt0 = __ldg(bt + Cb + c0), bt1 = __ldg(bt + Cb + c0 + 4);
                float bs0 = __ldg(bs + Cb + c0), bs1 = __ldg(bs + Cb + c0 + 4);
                float* At = acc[mf][2 * gs];
                float* Ag = acc[mf][2 * gs + 1];
                float4 v;
                v.x = gatem(At[0] + bt0, Ag[0] + bs0);
                v.y = gatem(At[1] + bt1, Ag[1] + bs1);
                v.z = gatem(At[2] + bt0, Ag[2] + bs0);
                v.w = gatem(At[3] + bt1, Ag[3] + bs1);
                *(float4*)(sm + (size_t)(Sb + mf * 1024 + G * 32) * 4) = v;
            }
    };

    float* outR = out;                                // res  [131072,128]
    float* outK = out + (size_t)131072 * 128;         // skip [131072,256]

    // ================= prologue =================
    zacc();
    loadX(); loadHalo(); loadChunk(0); cpcommit();
    loadChunk(1); cpcommit();

    // ================= gate pass 0 (ci 0..7) =================
#pragma unroll 1
    for (int kc = 0; kc < 8; ++kc) {
        CPWAIT(1); __syncthreads();
        if (kc < 4) mm256_t0(kc % 3, kc); else mm256(kc % 3, kc);
        loadChunk(kc + 2); cpcommit();
    }
    gate_epi(0);        // writes m q0..127 — disjoint from x (q128..255), no barrier
    zacc();

    // ================= gate pass 1 (ci 8..15) =================
#pragma unroll 1
    for (int kc = 0; kc < 8; ++kc) {
        int ci = 8 + kc;
        CPWAIT(1); __syncthreads();
        if (kc < 4) mm256_t0(ci % 3, kc); else mm256(ci % 3, kc);
        loadChunk(ci + 2); cpcommit();
    }
    __syncthreads();    // all warps done reading x
    gate_epi(1);        // overwrite x half with m q128..255
    zacc();

    // ================= out pass 0 (ci 16..23): res | skip 0..127 ==========
#pragma unroll 1
    for (int kc = 0; kc < 8; ++kc) {
        int ci = 16 + kc;
        CPWAIT(1); __syncthreads();   // also publishes gate_epi(1) on first iter
        mm256(ci % 3, kc);
        if (ci + 2 < 32) loadChunk(ci + 2);
        cpcommit();
    }
    {
#pragma unroll
        for (int mf = 0; mf < 4; ++mf) {
            long row0 = g0 + mw * 64 + mf * 16 + r0, row1 = row0 + 8;
#pragma unroll
            for (int nf = 0; nf < 4; ++nf) {
                int pcol = nw * 32 + nf * 8 + 2 * c0;
                float* A = acc[mf][nf];
                if (nw < 4) {
                    float b0 = __ldg(br + pcol), b1 = __ldg(br + pcol + 1);
                    float2 x0v = *(const float2*)(x + row0 * 128 + pcol);
                    float2 x1v = *(const float2*)(x + row1 * 128 + pcol);
                    *(float2*)(outR + row0 * 128 + pcol) =
                        make_float2(A[0] + b0 + x0v.x, A[1] + b1 + x0v.y);
                    *(float2*)(outR + row1 * 128 + pcol) =
                        make_float2(A[2] + b0 + x1v.x, A[3] + b1 + x1v.y);
                } else {
                    int ck = pcol - 128;
                    float b0 = __ldg(bk + ck), b1 = __ldg(bk + ck + 1);
                    *(float2*)(outK + row0 * 256 + ck) = make_float2(A[0] + b0, A[1] + b1);
                    *(float2*)(outK + row1 * 256 + ck) = make_float2(A[2] + b0, A[3] + b1);
                }
            }
        }
    }
    zacc();

    // ================= out pass 1 (ci 24..31): skip 128..255 =============
#pragma unroll 1
    for (int kc = 0; kc < 8; ++kc) {
        int ci = 24 + kc;
        CPWAIT(1); __syncthreads();
        mm128(ci % 3, kc);
        if (ci + 2 < 32) loadChunk(ci + 2);
        cpcommit();
    }
    {
#pragma unroll
        for (int mf = 0; mf < 2; ++mf) {
            long row0 = g0 + mw4 * 32 + mf * 16 + r0, row1 = row0 + 8;
#pragma unroll
            for (int nf = 0; nf < 4; ++nf) {
                int ck = 128 + nw4 * 32 + nf * 8 + 2 * c0;
                float* A = acc[mf][nf];
                float b0 = __ldg(bk + ck), b1 = __ldg(bk + ck + 1);
                *(float2*)(outK + row0 * 256 + ck) = make_float2(A[0] + b0, A[1] + b1);
                *(float2*)(outK + row1 * 256 + ck) = make_float2(A[2] + b0, A[3] + b1);
            }
        }
    }
}

// ------------------------------- launch ------------------------------------
extern "C" void kernel_launch(void* const* d_in, const int* in_sizes, int n_in,
                              void* d_out, int out_size) {
    const float* x  = (const float*)d_in[0];
    const float* wt = (const float*)d_in[1];
    const float* bt = (const float*)d_in[2];
    const float* ws = (const float*)d_in[3];
    const float* bs = (const float*)d_in[4];
    const float* wr = (const float*)d_in[5];
    const float* br = (const float*)d_in[6];
    const float* wk = (const float*)d_in[7];
    const float* bk = (const float*)d_in[8];
    float* out = (float*)d_out;

    cudaFuncSetAttribute(fused_kernel,
                         cudaFuncAttributeMaxDynamicSharedMemorySize, SMEM_BYTES);

    prep_kernel<<<896 + 8192, 256>>>(wt, ws, wr, wk, x);
    fused_kernel<<<1024, 512, SMEM_BYTES>>>(x, bt, bs, br, bk, out);
}

// round 8
// speedup vs baseline: 1.1157x; 1.1157x over previous
#include <cuda_runtime.h>
#include <cstdint>
#include <cstddef>

// ---------------------------------------------------------------------------
// WaveNet gated residual block, single fused kernel, tf32 mma.sync (sm_103
// baseline PTX — tcgen05 unavailable under compute_103).
//
// Structure = Round-5 winner; fragment path upgraded:
//   - x and m stored PLAIN row-major (8x16B groups per 32-float row,
//     group swizzle b ^= (row&7)); A-fragments loaded with ONE
//     ldmatrix.m8n8.x4.b16 per 16x8 tf32 fragment (reg = one tf32).
//   - B (weights) stay q-pair-packed; b-frag = one LDS.64 (R5 proven).
//   - gate weights channel-permuted so each thread's acc holds the (k,k+4)
//     channel pair -> gate epilogue = 32 conflict-free STS.32 into plain m.
// ---------------------------------------------------------------------------

#define DEVFN __device__ __forceinline__

// smem float offsets
static constexpr int MOFF = 0;         // m region: 128 x 256 floats (128 KB)
static constexpr int AOFF = 32768;     // A stages: 2 x 4096 floats (32 KB)
static constexpr int BOFF = 40960;     // B stages: 2 x 8192 floats (64 KB)
static constexpr int SMEM_BYTES = 57344 * 4;   // 229376

__device__ float wscratch[896 * 256];      // packed tf32 weights (896 KB)
__device__ float xscratch[131072 * 128];   // tf32-rounded plain x (64 MB)

// ------------------------------- helpers -----------------------------------
DEVFN uint32_t smaddr(const void* p) {
    uint32_t a;
    asm("{ .reg .u64 t; cvta.to.shared.u64 t, %1; cvt.u32.u64 %0, t; }" : "=r"(a) : "l"(p));
    return a;
}
DEVFN uint32_t tf32r(float x) { uint32_t u; asm("cvt.rna.tf32.f32 %0, %1;" : "=r"(u) : "f"(x)); return u; }
DEVFN float ex2f(float x) { float y; asm("ex2.approx.ftz.f32 %0, %1;" : "=f"(y) : "f"(x)); return y; }
DEVFN float rcpf(float x) { float y; asm("rcp.approx.ftz.f32 %0, %1;" : "=f"(y) : "f"(x)); return y; }

// tanh(a)*sigmoid(b) = (u-1)*v/((u+1)(v+1)), u=e^{2a}, v=e^{b}; clamped.
DEVFN float gatem(float a, float b) {
    a = fminf(fmaxf(a, -15.f), 15.f);
    b = fminf(fmaxf(b, -30.f), 30.f);
    float u = ex2f(a * 2.8853900817779268f);
    float v = ex2f(b * 1.4426950408889634f);
    float m = (u - 1.f) * v * rcpf((u + 1.f) * (v + 1.f));
    return __uint_as_float(tf32r(m));
}

DEVFN void cpa16(uint32_t dst, const void* src, int sz) {
    asm volatile("cp.async.cg.shared.global [%0], [%1], 16, %2;"
                 :: "r"(dst), "l"(src), "r"(sz) : "memory");
}
DEVFN void cpcommit() { asm volatile("cp.async.commit_group;" ::: "memory"); }
#define CPWAIT(n) asm volatile("cp.async.wait_group %0;" :: "n"(n) : "memory")

// m16n8k8 tf32 mma, row.col, f32 accum
DEVFN void mma8(float* d, const uint32_t* a, const uint32_t* b) {
    asm("mma.sync.aligned.m16n8k8.row.col.f32.tf32.tf32.f32 "
        "{%0,%1,%2,%3}, {%4,%5,%6,%7}, {%8,%9}, {%0,%1,%2,%3};"
        : "+f"(d[0]), "+f"(d[1]), "+f"(d[2]), "+f"(d[3])
        : "r"(a[0]), "r"(a[1]), "r"(a[2]), "r"(a[3]), "r"(b[0]), "r"(b[1]));
}

// ldmatrix x4: one full 16x8 tf32 A-fragment (b16 view, reg = one tf32)
DEVFN void ldsm4(uint32_t* r, uint32_t addr) {
    asm volatile("ldmatrix.sync.aligned.m8n8.x4.shared.b16 {%0,%1,%2,%3}, [%4];"
                 : "=r"(r[0]), "=r"(r[1]), "=r"(r[2]), "=r"(r[3]) : "r"(addr));
}

// ------------------------------ prep kernel --------------------------------
// wscratch rows (256 q-packed floats each, q(k)=(k&~7)+((k&3)<<1)+((k>>2)&1)):
//   0..511   gate: row = p*256 + t; G=t>>4, is_sig=(t>>3)&1, e=t&7,
//            channel C = p*128 + G*8 + (e>>1) + (e&1)*4  (pairing permutation)
//   512..767 out0: res 0..127 | skip 0..127
//   768..895 out1: skip 128..255
// xscratch: 128 PLAIN tf32 floats per token.
__global__ void __launch_bounds__(256)
prep_kernel(const float* __restrict__ wt, const float* __restrict__ ws,
            const float* __restrict__ wr, const float* __restrict__ wk,
            const float* __restrict__ x) {
    int bid = blockIdx.x, tid = threadIdx.x;
    if (bid < 896) {
        int idx = bid * 256 + tid;
        int row = idx >> 8, k = idx & 255;
        float v;
        if (row < 512) {
            int p = row >> 8, t = row & 255;
            int G = t >> 4, is_sig = (t >> 3) & 1, e = t & 7;
            int C = p * 128 + G * 8 + (e >> 1) + (e & 1) * 4;
            int src = ((k >> 7) * 128 + (k & 127)) * 256 + C;
            v = is_sig ? ws[src] : wt[src];
        } else if (row < 768) {
            int j = row - 512;
            v = (j < 128) ? wr[k * 128 + j] : wk[k * 256 + (j - 128)];
        } else {
            v = wk[k * 256 + 128 + (row - 768)];
        }
        int q = (k & ~7) + ((k & 3) << 1) + ((k >> 2) & 1);
        wscratch[row * 256 + q] = __uint_as_float(tf32r(v));
    } else {
        size_t g = (size_t)(bid - 896) * 256 + tid;   // < 2097152 groups of 8
        const float* src = x + g * 8;
        float4 lo = *(const float4*)src;
        float4 hi = *(const float4*)(src + 4);
        lo.x = __uint_as_float(tf32r(lo.x)); lo.y = __uint_as_float(tf32r(lo.y));
        lo.z = __uint_as_float(tf32r(lo.z)); lo.w = __uint_as_float(tf32r(lo.w));
        hi.x = __uint_as_float(tf32r(hi.x)); hi.y = __uint_as_float(tf32r(hi.y));
        hi.z = __uint_as_float(tf32r(hi.z)); hi.w = __uint_as_float(tf32r(hi.w));
        float* dst = xscratch + g * 8;
        *(float4*)dst = lo;
        *(float4*)(dst + 4) = hi;
    }
}

// ------------------------------ fused kernel -------------------------------
__global__ void __launch_bounds__(512, 1)
fused_kernel(const float* __restrict__ x,
             const float* __restrict__ bt, const float* __restrict__ bs,
             const float* __restrict__ br, const float* __restrict__ bk,
             float* __restrict__ out) {
    extern __shared__ float sm[];
    uint32_t sb = smaddr(sm);
    int tid = threadIdx.x, wid = tid >> 5, lid = tid & 31;
    int r0 = lid >> 2, c0 = lid & 3;
    int rx3 = r0 & 3;
    int tile = blockIdx.x;
    long g0 = (long)tile * 128;
    bool head = (tile & 127) == 0;          // first tile in a batch row

    // ldmatrix lane constants: lane supplies row (mrow) of matrix (l>>3)
    int mrow = ((lid >> 3) & 1) * 8 + (lid & 7);   // row within 16-row fragment
    int gh   = lid >> 4;                            // k-half (0: k0..3, 1: k4..7)
    int swl  = lid & 7;                             // (row & 7) for the swizzle

    float acc[4][4][4];

    // per-thread loader constants
    const int ldb = tid & 7, ldrow = tid >> 3;
    const uint32_t ldswzA = (uint32_t)(ldb ^ (ldrow & 7));        // A plain swizzle
    const uint32_t ldswzB = (uint32_t)(ldb ^ ((ldrow & 3) << 1)); // B q-pack swizzle

    auto loadA = [&](int kc, int st) {      // 128 rows x 32 k, plain + swizzle
#pragma unroll
        for (int i = 0; i < 2; ++i) {
            int row = ldrow + i * 64;
            const float* src = xscratch;
            int sz = 16;
            if (kc < 4) {
                if (head && row < 4) sz = 0;
                else src = xscratch + (g0 + row - 4) * 128 + kc * 32 + ldb * 4;
            } else {
                src = xscratch + (g0 + row) * 128 + (kc - 4) * 32 + ldb * 4;
            }
            cpa16(sb + (uint32_t)(AOFF + st * 4096 + row * 32 + ldswzA * 4) * 4, src, sz);
        }
    };
    auto loadB256 = [&](const float* wb, int kc, int st) {
#pragma unroll
        for (int i = 0; i < 4; ++i) {
            int row = ldrow + i * 64;
            const float* src = wb + row * 256 + kc * 32 + ldb * 4;
            cpa16(sb + (uint32_t)(BOFF + st * 8192 + row * 32 + ldswzB * 4) * 4, src, 16);
        }
    };
    auto loadB128 = [&](const float* wb, int kc, int st) {
#pragma unroll
        for (int i = 0; i < 2; ++i) {
            int row = ldrow + i * 64;
            const float* src = wb + row * 256 + kc * 32 + ldb * 4;
            cpa16(sb + (uint32_t)(BOFF + st * 8192 + row * 32 + ldswzB * 4) * 4, src, 16);
        }
    };

    auto zacc = [&]() {
#pragma unroll
        for (int i = 0; i < 4; ++i)
#pragma unroll
            for (int j = 0; j < 4; ++j)
#pragma unroll
                for (int q = 0; q < 4; ++q) acc[i][j][q] = 0.f;
    };

    // ---- gate compute: A from A-stage (row stride 32 floats) ----
    auto gate_compute = [&](int kc) {
        int mw = wid >> 3, nw = wid & 7;
        uint32_t Abase = sb + (uint32_t)(AOFF + (kc & 1) * 4096 + (mw * 64 + mrow) * 32) * 4;
        const float* Bs = sm + BOFF + (kc & 1) * 8192 + nw * 1024 + r0 * 32;
#pragma unroll
        for (int ks = 0; ks < 4; ++ks) {
            uint32_t xorw = (uint32_t)(((ks << 1) + gh) ^ swl) * 16;
            uint32_t a[4][4];
#pragma unroll
            for (int mf = 0; mf < 4; ++mf)
                ldsm4(a[mf], Abase + mf * 2048 + xorw);
            int o = ((ks ^ rx3) << 3) + 2 * c0;
#pragma unroll
            for (int nf = 0; nf < 4; ++nf) {
                float2 bv = *(const float2*)(Bs + nf * 256 + o);
                uint32_t b[2] = {__float_as_uint(bv.x), __float_as_uint(bv.y)};
#pragma unroll
                for (int mf = 0; mf < 4; ++mf) mma8(acc[mf][nf], a[mf], b);
            }
        }
    };
    // ---- out compute, 256 N rows: A from m region (row stride 256 floats) ----
    auto out_compute256 = [&](int kc) {
        int mw = wid >> 3, nw = wid & 7;
        uint32_t Abase = sb + (uint32_t)(MOFF + (mw * 64 + mrow) * 256 + kc * 32) * 4;
        const float* Bs = sm + BOFF + (kc & 1) * 8192 + nw * 1024 + r0 * 32;
#pragma unroll
        for (int ks = 0; ks < 4; ++ks) {
            uint32_t xorw = (uint32_t)(((ks << 1) + gh) ^ swl) * 16;
            uint32_t a[4][4];
#pragma unroll
            for (int mf = 0; mf < 4; ++mf)
                ldsm4(a[mf], Abase + mf * 16384 + xorw);
            int o = ((ks ^ rx3) << 3) + 2 * c0;
#pragma unroll
            for (int nf = 0; nf < 4; ++nf) {
                float2 bv = *(const float2*)(Bs + nf * 256 + o);
                uint32_t b[2] = {__float_as_uint(bv.x), __float_as_uint(bv.y)};
#pragma unroll
                for (int mf = 0; mf < 4; ++mf) mma8(acc[mf][nf], a[mf], b);
            }
        }
    };
    // ---- out compute, 128 N rows (4M x 4N) ----
    auto out_compute128 = [&](int kc) {
        int mw4 = wid >> 2, nw4 = wid & 3;
        uint32_t Abase = sb + (uint32_t)(MOFF + (mw4 * 32 + mrow) * 256 + kc * 32) * 4;
        const float* Bs = sm + BOFF + (kc & 1) * 8192 + nw4 * 1024 + r0 * 32;
#pragma unroll
        for (int ks = 0; ks < 4; ++ks) {
            uint32_t xorw = (uint32_t)(((ks << 1) + gh) ^ swl) * 16;
            uint32_t a[2][4];
#pragma unroll
            for (int mf = 0; mf < 2; ++mf)
                ldsm4(a[mf], Abase + mf * 16384 + xorw);
            int o = ((ks ^ rx3) << 3) + 2 * c0;
#pragma unroll
            for (int nf = 0; nf < 4; ++nf) {
                float2 bv = *(const float2*)(Bs + nf * 256 + o);
                uint32_t b[2] = {__float_as_uint(bv.x), __float_as_uint(bv.y)};
#pragma unroll
                for (int mf = 0; mf < 2; ++mf) mma8(acc[mf][nf], a[mf], b);
            }
        }
    };

    // ---- gate epilogue: plain m stores (conflict-free STS.32) ----
    // thread holds channels (G*8+c0, G*8+c0+4) for rows (rA, rA+8).
    auto gate_epi = [&](int p) {
        int mw = wid >> 3, nw = wid & 7;
#pragma unroll
        for (int mf = 0; mf < 4; ++mf) {
            int rA = mw * 64 + mf * 16 + r0;
            float* m0 = sm + MOFF + rA * 256;
            float* m1 = m0 + 8 * 256;
#pragma unroll
            for (int gs = 0; gs < 2; ++gs) {
                int G = nw * 2 + gs;
                int Cb = p * 128 + G * 8;
                float bt0 = __ldg(bt + Cb + c0), bt1 = __ldg(bt + Cb + c0 + 4);
                float bs0 = __ldg(bs + Cb + c0), bs1 = __ldg(bs + Cb + c0 + 4);
                float* At = acc[mf][2 * gs];
                float* Ag = acc[mf][2 * gs + 1];
                int kcblk = p * 4 + (G >> 2);
                int bb = (G & 3) * 2;
                int o0 = kcblk * 32 + ((bb)     ^ r0) * 4 + c0;
                int o1 = kcblk * 32 + ((bb + 1) ^ r0) * 4 + c0;
                m0[o0] = gatem(At[0] + bt0, Ag[0] + bs0);
                m0[o1] = gatem(At[1] + bt1, Ag[1] + bs1);
                m1[o0] = gatem(At[2] + bt0, Ag[2] + bs0);
                m1[o1] = gatem(At[3] + bt1, Ag[3] + bs1);
            }
        }
    };

    const float* wg0 = wscratch;
    const float* wg1 = wscratch + 256 * 256;
    const float* wo0 = wscratch + 512 * 256;
    const float* wo1 = wscratch + 768 * 256;
    float* outR = out;                                // res  [131072,128]
    float* outK = out + (size_t)131072 * 128;         // skip [131072,256]

    // ================= gate pass 0 =================
    zacc();
    loadA(0, 0); loadB256(wg0, 0, 0); cpcommit();
    loadA(1, 1); loadB256(wg0, 1, 1); cpcommit();
#pragma unroll 1
    for (int kc = 0; kc < 8; ++kc) {
        CPWAIT(1);
        __syncthreads();
        gate_compute(kc);
        __syncthreads();
        if (kc < 6) { loadA(kc + 2, kc & 1); loadB256(wg0, kc + 2, kc & 1); }
        cpcommit();
    }
    loadA(0, 0); loadB256(wg1, 0, 0); cpcommit();
    loadA(1, 1); loadB256(wg1, 1, 1); cpcommit();
    gate_epi(0);

    // ================= gate pass 1 =================
    zacc();
#pragma unroll 1
    for (int kc = 0; kc < 8; ++kc) {
        CPWAIT(1);
        __syncthreads();
        gate_compute(kc);
        __syncthreads();
        if (kc < 6) { loadA(kc + 2, kc & 1); loadB256(wg1, kc + 2, kc & 1); }
        cpcommit();
    }
    loadB256(wo0, 0, 0); cpcommit();
    loadB256(wo0, 1, 1); cpcommit();
    gate_epi(1);

    // ================= out pass 0 (res | skip 0..127) =================
    zacc();
#pragma unroll 1
    for (int kc = 0; kc < 8; ++kc) {
        CPWAIT(1);
        __syncthreads();        // first iter also publishes gate_epi stores
        out_compute256(kc);
        __syncthreads();
        if (kc < 6) loadB256(wo0, kc + 2, kc & 1);
        cpcommit();
    }
    loadB128(wo1, 0, 0); cpcommit();
    loadB128(wo1, 1, 1); cpcommit();
    {
        int mw = wid >> 3, nw = wid & 7;
#pragma unroll
        for (int mf = 0; mf < 4; ++mf) {
            long row0 = g0 + mw * 64 + mf * 16 + r0, row1 = row0 + 8;
#pragma unroll
            for (int nf = 0; nf < 4; ++nf) {
                int pcol = nw * 32 + nf * 8 + 2 * c0;
                float* A = acc[mf][nf];
                if (nw < 4) {
                    float b0 = __ldg(br + pcol), b1 = __ldg(br + pcol + 1);
                    float2 x0v = *(const float2*)(x + row0 * 128 + pcol);
                    float2 x1v = *(const float2*)(x + row1 * 128 + pcol);
                    *(float2*)(outR + row0 * 128 + pcol) =
                        make_float2(A[0] + b0 + x0v.x, A[1] + b1 + x0v.y);
                    *(float2*)(outR + row1 * 128 + pcol) =
                        make_float2(A[2] + b0 + x1v.x, A[3] + b1 + x1v.y);
                } else {
                    int ck = pcol - 128;
                    float b0 = __ldg(bk + ck), b1 = __ldg(bk + ck + 1);
                    *(float2*)(outK + row0 * 256 + ck) = make_float2(A[0] + b0, A[1] + b1);
                    *(float2*)(outK + row1 * 256 + ck) = make_float2(A[2] + b0, A[3] + b1);
                }
            }
        }
    }

    // ================= out pass 1 (skip 128..255) =================
#pragma unroll
    for (int i = 0; i < 2; ++i)
#pragma unroll
        for (int j = 0; j < 4; ++j)
#pragma unroll
            for (int q = 0; q < 4; ++q) acc[i][j][q] = 0.f;
#pragma unroll 1
    for (int kc = 0; kc < 8; ++kc) {
        CPWAIT(1);
        __syncthreads();
        out_compute128(kc);
        __syncthreads();
        if (kc < 6) loadB128(wo1, kc + 2, kc & 1);
        cpcommit();
    }
    {
        int mw4 = wid >> 2, nw4 = wid & 3;
#pragma unroll
        for (int mf = 0; mf < 2; ++mf) {
            long row0 = g0 + mw4 * 32 + mf * 16 + r0, row1 = row0 + 8;
#pragma unroll
            for (int nf = 0; nf < 4; ++nf) {
                int ck = 128 + nw4 * 32 + nf * 8 + 2 * c0;
                float* A = acc[mf][nf];
                float b0 = __ldg(bk + ck), b1 = __ldg(bk + ck + 1);
                *(float2*)(outK + row0 * 256 + ck) = make_float2(A[0] + b0, A[1] + b1);
                *(float2*)(outK + row1 * 256 + ck) = make_float2(A[2] + b0, A[3] + b1);
            }
        }
    }
}

// ------------------------------- launch ------------------------------------
extern "C" void kernel_launch(void* const* d_in, const int* in_sizes, int n_in,
                              void* d_out, int out_size) {
    const float* x  = (const float*)d_in[0];
    const float* wt = (const float*)d_in[1];
    const float* bt = (const float*)d_in[2];
    const float* ws = (const float*)d_in[3];
    const float* bs = (const float*)d_in[4];
    const float* wr = (const float*)d_in[5];
    const float* br = (const float*)d_in[6];
    const float* wk = (const float*)d_in[7];
    const float* bk = (const float*)d_in[8];
    float* out = (float*)d_out;

    cudaFuncSetAttribute(fused_kernel,
                         cudaFuncAttributeMaxDynamicSharedMemorySize, SMEM_BYTES);

    prep_kernel<<<896 + 8192, 256>>>(wt, ws, wr, wk, x);
    fused_kernel<<<1024, 512, SMEM_BYTES>>>(x, bt, bs, br, bk, out);
}

// round 9
// speedup vs baseline: 1.1260x; 1.0092x over previous
#include <cuda_runtime.h>
#include <cstdint>
#include <cstddef>

// ---------------------------------------------------------------------------
// WaveNet gated residual block, single fused kernel, tf32 mma.sync (sm_103
// baseline PTX — tcgen05 unavailable under compute_103).
//
// R8 = R7 compute (ldmatrix A-path) + single-barrier 3-stage cp.async ring.
//   - B weights stream through 3 x 32KB stages, ONE __syncthreads per chunk.
//   - A stages (gate passes) live inside the m region's second half
//     (cols 128..255), which is dead until gate_epi(1) overwrites it with m.
//   - chunk schedule ci = 0..31: pass = ci>>3 (gate0, gate1, out0, out1),
//     kc = ci&7, stage = ci%3 for both A and B.
// ---------------------------------------------------------------------------

#define DEVFN __device__ __forceinline__

// smem float offsets
static constexpr int MOFF = 0;         // m region: 128 x 256 floats (128 KB)
                                       //   gate phase: cols 128..255 hold A stages
static constexpr int BOFF = 32768;     // B stages: 3 x 8192 floats (96 KB)
static constexpr int SMEM_BYTES = 57344 * 4;   // 229376

__device__ float wscratch[896 * 256];      // packed tf32 weights (896 KB)
__device__ float xscratch[131072 * 128];   // tf32-rounded plain x (64 MB)

// ------------------------------- helpers -----------------------------------
DEVFN uint32_t smaddr(const void* p) {
    uint32_t a;
    asm("{ .reg .u64 t; cvta.to.shared.u64 t, %1; cvt.u32.u64 %0, t; }" : "=r"(a) : "l"(p));
    return a;
}
DEVFN uint32_t tf32r(float x) { uint32_t u; asm("cvt.rna.tf32.f32 %0, %1;" : "=r"(u) : "f"(x)); return u; }
DEVFN float ex2f(float x) { float y; asm("ex2.approx.ftz.f32 %0, %1;" : "=f"(y) : "f"(x)); return y; }
DEVFN float rcpf(float x) { float y; asm("rcp.approx.ftz.f32 %0, %1;" : "=f"(y) : "f"(x)); return y; }

// tanh(a)*sigmoid(b) = (u-1)*v/((u+1)(v+1)), u=e^{2a}, v=e^{b}; clamped.
DEVFN float gatem(float a, float b) {
    a = fminf(fmaxf(a, -15.f), 15.f);
    b = fminf(fmaxf(b, -30.f), 30.f);
    float u = ex2f(a * 2.8853900817779268f);
    float v = ex2f(b * 1.4426950408889634f);
    float m = (u - 1.f) * v * rcpf((u + 1.f) * (v + 1.f));
    return __uint_as_float(tf32r(m));
}

DEVFN void cpa16(uint32_t dst, const void* src, int sz) {
    asm volatile("cp.async.cg.shared.global [%0], [%1], 16, %2;"
                 :: "r"(dst), "l"(src), "r"(sz) : "memory");
}
DEVFN void cpcommit() { asm volatile("cp.async.commit_group;" ::: "memory"); }
#define CPWAIT(n) asm volatile("cp.async.wait_group %0;" :: "n"(n) : "memory")

// m16n8k8 tf32 mma, row.col, f32 accum
DEVFN void mma8(float* d, const uint32_t* a, const uint32_t* b) {
    asm("mma.sync.aligned.m16n8k8.row.col.f32.tf32.tf32.f32 "
        "{%0,%1,%2,%3}, {%4,%5,%6,%7}, {%8,%9}, {%0,%1,%2,%3};"
        : "+f"(d[0]), "+f"(d[1]), "+f"(d[2]), "+f"(d[3])
        : "r"(a[0]), "r"(a[1]), "r"(a[2]), "r"(a[3]), "r"(b[0]), "r"(b[1]));
}

// ldmatrix x4: one full 16x8 tf32 A-fragment (b16 view, reg = one tf32)
DEVFN void ldsm4(uint32_t* r, uint32_t addr) {
    asm volatile("ldmatrix.sync.aligned.m8n8.x4.shared.b16 {%0,%1,%2,%3}, [%4];"
                 : "=r"(r[0]), "=r"(r[1]), "=r"(r[2]), "=r"(r[3]) : "r"(addr));
}

// ------------------------------ prep kernel --------------------------------
// wscratch rows (256 q-packed floats each, q(k)=(k&~7)+((k&3)<<1)+((k>>2)&1)):
//   0..511   gate: row = p*256 + t; G=t>>4, is_sig=(t>>3)&1, e=t&7,
//            channel C = p*128 + G*8 + (e>>1) + (e&1)*4  (pairing permutation)
//   512..767 out0: res 0..127 | skip 0..127
//   768..895 out1: skip 128..255
// xscratch: 128 PLAIN tf32 floats per token.
__global__ void __launch_bounds__(256)
prep_kernel(const float* __restrict__ wt, const float* __restrict__ ws,
            const float* __restrict__ wr, const float* __restrict__ wk,
            const float* __restrict__ x) {
    int bid = blockIdx.x, tid = threadIdx.x;
    if (bid < 896) {
        int idx = bid * 256 + tid;
        int row = idx >> 8, k = idx & 255;
        float v;
        if (row < 512) {
            int p = row >> 8, t = row & 255;
            int G = t >> 4, is_sig = (t >> 3) & 1, e = t & 7;
            int C = p * 128 + G * 8 + (e >> 1) + (e & 1) * 4;
            int src = ((k >> 7) * 128 + (k & 127)) * 256 + C;
            v = is_sig ? ws[src] : wt[src];
        } else if (row < 768) {
            int j = row - 512;
            v = (j < 128) ? wr[k * 128 + j] : wk[k * 256 + (j - 128)];
        } else {
            v = wk[k * 256 + 128 + (row - 768)];
        }
        int q = (k & ~7) + ((k & 3) << 1) + ((k >> 2) & 1);
        wscratch[row * 256 + q] = __uint_as_float(tf32r(v));
    } else {
        size_t g = (size_t)(bid - 896) * 256 + tid;   // < 2097152 groups of 8
        const float* src = x + g * 8;
        float4 lo = *(const float4*)src;
        float4 hi = *(const float4*)(src + 4);
        lo.x = __uint_as_float(tf32r(lo.x)); lo.y = __uint_as_float(tf32r(lo.y));
        lo.z = __uint_as_float(tf32r(lo.z)); lo.w = __uint_as_float(tf32r(lo.w));
        hi.x = __uint_as_float(tf32r(hi.x)); hi.y = __uint_as_float(tf32r(hi.y));
        hi.z = __uint_as_float(tf32r(hi.z)); hi.w = __uint_as_float(tf32r(hi.w));
        float* dst = xscratch + g * 8;
        *(float4*)dst = lo;
        *(float4*)(dst + 4) = hi;
    }
}

// ------------------------------ fused kernel -------------------------------
__global__ void __launch_bounds__(512, 1)
fused_kernel(const float* __restrict__ x,
             const float* __restrict__ bt, const float* __restrict__ bs,
             const float* __restrict__ br, const float* __restrict__ bk,
             float* __restrict__ out) {
    extern __shared__ float sm[];
    uint32_t sb = smaddr(sm);
    int tid = threadIdx.x, wid = tid >> 5, lid = tid & 31;
    int r0 = lid >> 2, c0 = lid & 3;
    int rx3 = r0 & 3;
    int tile = blockIdx.x;
    long g0 = (long)tile * 128;
    bool head = (tile & 127) == 0;          // first tile in a batch row

    // ldmatrix lane constants
    int mrow = ((lid >> 3) & 1) * 8 + (lid & 7);   // row within 16-row fragment
    int gh   = lid >> 4;                            // k-half
    int swl  = lid & 7;                             // row&7 for swizzle

    float acc[4][4][4];

    // per-thread loader constants
    const int ldb = tid & 7, ldrow = tid >> 3;      // ldrow 0..63
    const uint32_t ldswzA = (uint32_t)(ldb ^ (ldrow & 7));
    const uint32_t ldswzB = (uint32_t)(ldb ^ ((ldrow & 3) << 1));

    // ---- unified chunk loader: ci = 0..31, pass=ci>>3, kc=ci&7, st=ci%3 ----
    auto loadChunk = [&](int ci) {
        if (ci >= 32) return;
        int pass = ci >> 3, kc = ci & 7, st = ci % 3;
        if (pass < 2) {
            // A chunk (x tile, tap handled here): into m cols 128+st*32
#pragma unroll
            for (int i = 0; i < 2; ++i) {
                int row = ldrow + i * 64;
                const float* srcA = xscratch;
                int sz = 16;
                if (kc < 4) {
                    if (head && row < 4) sz = 0;
                    else srcA = xscratch + (g0 + row - 4) * 128 + kc * 32 + ldb * 4;
                } else {
                    srcA = xscratch + (g0 + row) * 128 + (kc - 4) * 32 + ldb * 4;
                }
                cpa16(sb + (uint32_t)(MOFF + row * 256 + 128 + st * 32 + ldswzA * 4) * 4,
                      srcA, sz);
            }
            // B chunk: 256 rows
            const float* wb = wscratch + pass * 65536;
#pragma unroll
            for (int i = 0; i < 4; ++i) {
                int row = ldrow + i * 64;
                cpa16(sb + (uint32_t)(BOFF + st * 8192 + row * 32 + ldswzB * 4) * 4,
                      wb + row * 256 + kc * 32 + ldb * 4, 16);
            }
        } else if (pass == 2) {
            const float* wb = wscratch + 512 * 256;
#pragma unroll
            for (int i = 0; i < 4; ++i) {
                int row = ldrow + i * 64;
                cpa16(sb + (uint32_t)(BOFF + st * 8192 + row * 32 + ldswzB * 4) * 4,
                      wb + row * 256 + kc * 32 + ldb * 4, 16);
            }
        } else {
            const float* wb = wscratch + 768 * 256;
#pragma unroll
            for (int i = 0; i < 2; ++i) {
                int row = ldrow + i * 64;
                cpa16(sb + (uint32_t)(BOFF + st * 8192 + row * 32 + ldswzB * 4) * 4,
                      wb + row * 256 + kc * 32 + ldb * 4, 16);
            }
        }
    };

    auto zacc = [&]() {
#pragma unroll
        for (int i = 0; i < 4; ++i)
#pragma unroll
            for (int j = 0; j < 4; ++j)
#pragma unroll
                for (int q = 0; q < 4; ++q) acc[i][j][q] = 0.f;
    };

    // ---- gate compute: A from m-region stage (row stride 256, col 128+st*32) ----
    auto gate_compute = [&](int st) {
        int mw = wid >> 3, nw = wid & 7;
        uint32_t Abase = sb + (uint32_t)(MOFF + (mw * 64 + mrow) * 256 + 128 + st * 32) * 4;
        const float* Bs = sm + BOFF + st * 8192 + nw * 1024 + r0 * 32;
#pragma unroll
        for (int ks = 0; ks < 4; ++ks) {
            uint32_t xorw = (uint32_t)(((ks << 1) + gh) ^ swl) * 16;
            uint32_t a[4][4];
#pragma unroll
            for (int mf = 0; mf < 4; ++mf)
                ldsm4(a[mf], Abase + mf * 16384 + xorw);
            int o = ((ks ^ rx3) << 3) + 2 * c0;
#pragma unroll
            for (int nf = 0; nf < 4; ++nf) {
                float2 bv = *(const float2*)(Bs + nf * 256 + o);
                uint32_t b[2] = {__float_as_uint(bv.x), __float_as_uint(bv.y)};
#pragma unroll
                for (int mf = 0; mf < 4; ++mf) mma8(acc[mf][nf], a[mf], b);
            }
        }
    };
    // ---- out compute, 256 N rows ----
    auto out_compute256 = [&](int kc, int st) {
        int mw = wid >> 3, nw = wid & 7;
        uint32_t Abase = sb + (uint32_t)(MOFF + (mw * 64 + mrow) * 256 + kc * 32) * 4;
        const float* Bs = sm + BOFF + st * 8192 + nw * 1024 + r0 * 32;
#pragma unroll
        for (int ks = 0; ks < 4; ++ks) {
            uint32_t xorw = (uint32_t)(((ks << 1) + gh) ^ swl) * 16;
            uint32_t a[4][4];
#pragma unroll
            for (int mf = 0; mf < 4; ++mf)
                ldsm4(a[mf], Abase + mf * 16384 + xorw);
            int o = ((ks ^ rx3) << 3) + 2 * c0;
#pragma unroll
            for (int nf = 0; nf < 4; ++nf) {
                float2 bv = *(const float2*)(Bs + nf * 256 + o);
                uint32_t b[2] = {__float_as_uint(bv.x), __float_as_uint(bv.y)};
#pragma unroll
                for (int mf = 0; mf < 4; ++mf) mma8(acc[mf][nf], a[mf], b);
            }
        }
    };
    // ---- out compute, 128 N rows (4M x 4N) ----
    auto out_compute128 = [&](int kc, int st) {
        int mw4 = wid >> 2, nw4 = wid & 3;
        uint32_t Abase = sb + (uint32_t)(MOFF + (mw4 * 32 + mrow) * 256 + kc * 32) * 4;
        const float* Bs = sm + BOFF + st * 8192 + nw4 * 1024 + r0 * 32;
#pragma unroll
        for (int ks = 0; ks < 4; ++ks) {
            uint32_t xorw = (uint32_t)(((ks << 1) + gh) ^ swl) * 16;
            uint32_t a[2][4];
#pragma unroll
            for (int mf = 0; mf < 2; ++mf)
                ldsm4(a[mf], Abase + mf * 16384 + xorw);
            int o = ((ks ^ rx3) << 3) + 2 * c0;
#pragma unroll
            for (int nf = 0; nf < 4; ++nf) {
                float2 bv = *(const float2*)(Bs + nf * 256 + o);
                uint32_t b[2] = {__float_as_uint(bv.x), __float_as_uint(bv.y)};
#pragma unroll
                for (int mf = 0; mf < 2; ++mf) mma8(acc[mf][nf], a[mf], b);
            }
        }
    };

    // ---- gate epilogue: plain m stores (conflict-free STS.32) ----
    auto gate_epi = [&](int p) {
        int mw = wid >> 3, nw = wid & 7;
#pragma unroll
        for (int mf = 0; mf < 4; ++mf) {
            int rA = mw * 64 + mf * 16 + r0;
            float* m0 = sm + MOFF + rA * 256;
            float* m1 = m0 + 8 * 256;
#pragma unroll
            for (int gs = 0; gs < 2; ++gs) {
                int G = nw * 2 + gs;
                int Cb = p * 128 + G * 8;
                float bt0 = __ldg(bt + Cb + c0), bt1 = __ldg(bt + Cb + c0 + 4);
                float bs0 = __ldg(bs + Cb + c0), bs1 = __ldg(bs + Cb + c0 + 4);
                float* At = acc[mf][2 * gs];
                float* Ag = acc[mf][2 * gs + 1];
                int kcblk = p * 4 + (G >> 2);
                int bb = (G & 3) * 2;
                int o0 = kcblk * 32 + ((bb)     ^ r0) * 4 + c0;
                int o1 = kcblk * 32 + ((bb + 1) ^ r0) * 4 + c0;
                m0[o0] = gatem(At[0] + bt0, Ag[0] + bs0);
                m0[o1] = gatem(At[1] + bt1, Ag[1] + bs1);
                m1[o0] = gatem(At[2] + bt0, Ag[2] + bs0);
                m1[o1] = gatem(At[3] + bt1, Ag[3] + bs1);
            }
        }
    };

    float* outR = out;                                // res  [131072,128]
    float* outK = out + (size_t)131072 * 128;         // skip [131072,256]

    // ================= prologue =================
    zacc();
    loadChunk(0); cpcommit();
    loadChunk(1); cpcommit();

    // ================= gate pass 0 (ci 0..7) =================
#pragma unroll 1
    for (int ci = 0; ci < 8; ++ci) {
        CPWAIT(1); __syncthreads();
        gate_compute(ci % 3);
        loadChunk(ci + 2); cpcommit();
    }
    gate_epi(0);        // writes m cols 0..127; disjoint from A stages & B
    zacc();

    // ================= gate pass 1 (ci 8..15) =================
#pragma unroll 1
    for (int ci = 8; ci < 16; ++ci) {
        CPWAIT(1); __syncthreads();
        gate_compute(ci % 3);
        loadChunk(ci + 2); cpcommit();
    }
    __syncthreads();    // all warps done reading A stages (m cols 128..255)
    gate_epi(1);        // overwrite with m cols 128..255
    zacc();

    // ================= out pass 0 (ci 16..23): res | skip 0..127 ==========
#pragma unroll 1
    for (int ci = 16; ci < 24; ++ci) {
        CPWAIT(1); __syncthreads();   // first iter publishes gate_epi(1)
        out_compute256(ci & 7, ci % 3);
        loadChunk(ci + 2); cpcommit();
    }
    {
        int mw = wid >> 3, nw = wid & 7;
#pragma unroll
        for (int mf = 0; mf < 4; ++mf) {
            long row0 = g0 + mw * 64 + mf * 16 + r0, row1 = row0 + 8;
#pragma unroll
            for (int nf = 0; nf < 4; ++nf) {
                int pcol = nw * 32 + nf * 8 + 2 * c0;
                float* A = acc[mf][nf];
                if (nw < 4) {
                    float b0 = __ldg(br + pcol), b1 = __ldg(br + pcol + 1);
                    float2 x0v = *(const float2*)(x + row0 * 128 + pcol);
                    float2 x1v = *(const float2*)(x + row1 * 128 + pcol);
                    *(float2*)(outR + row0 * 128 + pcol) =
                        make_float2(A[0] + b0 + x0v.x, A[1] + b1 + x0v.y);
                    *(float2*)(outR + row1 * 128 + pcol) =
                        make_float2(A[2] + b0 + x1v.x, A[3] + b1 + x1v.y);
                } else {
                    int ck = pcol - 128;
                    float b0 = __ldg(bk + ck), b1 = __ldg(bk + ck + 1);
                    *(float2*)(outK + row0 * 256 + ck) = make_float2(A[0] + b0, A[1] + b1);
                    *(float2*)(outK + row1 * 256 + ck) = make_float2(A[2] + b0, A[3] + b1);
                }
            }
        }
    }
    zacc();

    // ================= out pass 1 (ci 24..31): skip 128..255 =============
#pragma unroll 1
    for (int ci = 24; ci < 32; ++ci) {
        CPWAIT(1); __syncthreads();
        out_compute128(ci & 7, ci % 3);
        loadChunk(ci + 2); cpcommit();
    }
    {
        int mw4 = wid >> 2, nw4 = wid & 3;
#pragma unroll
        for (int mf = 0; mf < 2; ++mf) {
            long row0 = g0 + mw4 * 32 + mf * 16 + r0, row1 = row0 + 8;
#pragma unroll
            for (int nf = 0; nf < 4; ++nf) {
                int ck = 128 + nw4 * 32 + nf * 8 + 2 * c0;
                float* A = acc[mf][nf];
                float b0 = __ldg(bk + ck), b1 = __ldg(bk + ck + 1);
                *(float2*)(outK + row0 * 256 + ck) = make_float2(A[0] + b0, A[1] + b1);
                *(float2*)(outK + row1 * 256 + ck) = make_float2(A[2] + b0, A[3] + b1);
            }
        }
    }
}

// ------------------------------- launch ------------------------------------
extern "C" void kernel_launch(void* const* d_in, const int* in_sizes, int n_in,
                              void* d_out, int out_size) {
    const float* x  = (const float*)d_in[0];
    const float* wt = (const float*)d_in[1];
    const float* bt = (const float*)d_in[2];
    const float* ws = (const float*)d_in[3];
    const float* bs = (const float*)d_in[4];
    const float* wr = (const float*)d_in[5];
    const float* br = (const float*)d_in[6];
    const float* wk = (const float*)d_in[7];
    const float* bk = (const float*)d_in[8];
    float* out = (float*)d_out;

    cudaFuncSetAttribute(fused_kernel,
                         cudaFuncAttributeMaxDynamicSharedMemorySize, SMEM_BYTES);

    prep_kernel<<<896 + 8192, 256>>>(wt, ws, wr, wk, x);
    fused_kernel<<<1024, 512, SMEM_BYTES>>>(x, bt, bs, br, bk, out);
}

// round 11
// speedup vs baseline: 1.1580x; 1.0284x over previous
#include <cuda_runtime.h>
#include <cstdint>
#include <cstddef>

// ---------------------------------------------------------------------------
// WaveNet gated residual block, single fused kernel, tf32 mma.sync (sm_103
// baseline PTX — tcgen05 unavailable under compute_103).
//
// R9 = R8 pipeline (3-stage single-barrier cp.async ring, ldmatrix A-path)
// with 8 warps x 64x64 warp tiles (256 threads, 2M x 4N):
//   - halves cross-warp A-fragment duplication (smem wavefronts/kc -30%)
//   - doubles per-warp MMA run length between fragment loads
// ---------------------------------------------------------------------------

#define DEVFN __device__ __forceinline__

// smem float offsets
static constexpr int MOFF = 0;         // m region: 128 x 256 floats (128 KB)
                                       //   gate phase: cols 128..255 hold A stages
static constexpr int BOFF = 32768;     // B stages: 3 x 8192 floats (96 KB)
static constexpr int SMEM_BYTES = 57344 * 4;   // 229376

__device__ float wscratch[896 * 256];      // packed tf32 weights (896 KB)
__device__ float xscratch[131072 * 128];   // tf32-rounded plain x (64 MB)

// ------------------------------- helpers -----------------------------------
DEVFN uint32_t smaddr(const void* p) {
    uint32_t a;
    asm("{ .reg .u64 t; cvta.to.shared.u64 t, %1; cvt.u32.u64 %0, t; }" : "=r"(a) : "l"(p));
    return a;
}
DEVFN uint32_t tf32r(float x) { uint32_t u; asm("cvt.rna.tf32.f32 %0, %1;" : "=r"(u) : "f"(x)); return u; }
DEVFN float ex2f(float x) { float y; asm("ex2.approx.ftz.f32 %0, %1;" : "=f"(y) : "f"(x)); return y; }
DEVFN float rcpf(float x) { float y; asm("rcp.approx.ftz.f32 %0, %1;" : "=f"(y) : "f"(x)); return y; }

// tanh(a)*sigmoid(b) = (u-1)*v/((u+1)(v+1)), u=e^{2a}, v=e^{b}; clamped.
DEVFN float gatem(float a, float b) {
    a = fminf(fmaxf(a, -15.f), 15.f);
    b = fminf(fmaxf(b, -30.f), 30.f);
    float u = ex2f(a * 2.8853900817779268f);
    float v = ex2f(b * 1.4426950408889634f);
    float m = (u - 1.f) * v * rcpf((u + 1.f) * (v + 1.f));
    return __uint_as_float(tf32r(m));
}

DEVFN void cpa16(uint32_t dst, const void* src, int sz) {
    asm volatile("cp.async.cg.shared.global [%0], [%1], 16, %2;"
                 :: "r"(dst), "l"(src), "r"(sz) : "memory");
}
DEVFN void cpcommit() { asm volatile("cp.async.commit_group;" ::: "memory"); }
#define CPWAIT(n) asm volatile("cp.async.wait_group %0;" :: "n"(n) : "memory")

// m16n8k8 tf32 mma, row.col, f32 accum
DEVFN void mma8(float* d, const uint32_t* a, const uint32_t* b) {
    asm("mma.sync.aligned.m16n8k8.row.col.f32.tf32.tf32.f32 "
        "{%0,%1,%2,%3}, {%4,%5,%6,%7}, {%8,%9}, {%0,%1,%2,%3};"
        : "+f"(d[0]), "+f"(d[1]), "+f"(d[2]), "+f"(d[3])
        : "r"(a[0]), "r"(a[1]), "r"(a[2]), "r"(a[3]), "r"(b[0]), "r"(b[1]));
}

// ldmatrix x4: one full 16x8 tf32 A-fragment (b16 view, reg = one tf32)
DEVFN void ldsm4(uint32_t* r, uint32_t addr) {
    asm volatile("ldmatrix.sync.aligned.m8n8.x4.shared.b16 {%0,%1,%2,%3}, [%4];"
                 : "=r"(r[0]), "=r"(r[1]), "=r"(r[2]), "=r"(r[3]) : "r"(addr));
}

// ------------------------------ prep kernel --------------------------------
// wscratch rows (256 q-packed floats each, q(k)=(k&~7)+((k&3)<<1)+((k>>2)&1)):
//   0..511   gate: row = p*256 + t; G=t>>4, is_sig=(t>>3)&1, e=t&7,
//            channel C = p*128 + G*8 + (e>>1) + (e&1)*4  (pairing permutation)
//   512..767 out0: res 0..127 | skip 0..127
//   768..895 out1: skip 128..255
// xscratch: 128 PLAIN tf32 floats per token.
__global__ void __launch_bounds__(256)
prep_kernel(const float* __restrict__ wt, const float* __restrict__ ws,
            const float* __restrict__ wr, const float* __restrict__ wk,
            const float* __restrict__ x) {
    int bid = blockIdx.x, tid = threadIdx.x;
    if (bid < 896) {
        int idx = bid * 256 + tid;
        int row = idx >> 8, k = idx & 255;
        float v;
        if (row < 512) {
            int p = row >> 8, t = row & 255;
            int G = t >> 4, is_sig = (t >> 3) & 1, e = t & 7;
            int C = p * 128 + G * 8 + (e >> 1) + (e & 1) * 4;
            int src = ((k >> 7) * 128 + (k & 127)) * 256 + C;
            v = is_sig ? ws[src] : wt[src];
        } else if (row < 768) {
            int j = row - 512;
            v = (j < 128) ? wr[k * 128 + j] : wk[k * 256 + (j - 128)];
        } else {
            v = wk[k * 256 + 128 + (row - 768)];
        }
        int q = (k & ~7) + ((k & 3) << 1) + ((k >> 2) & 1);
        wscratch[row * 256 + q] = __uint_as_float(tf32r(v));
    } else {
        size_t g = (size_t)(bid - 896) * 256 + tid;   // < 2097152 groups of 8
        const float* src = x + g * 8;
        float4 lo = *(const float4*)src;
        float4 hi = *(const float4*)(src + 4);
        lo.x = __uint_as_float(tf32r(lo.x)); lo.y = __uint_as_float(tf32r(lo.y));
        lo.z = __uint_as_float(tf32r(lo.z)); lo.w = __uint_as_float(tf32r(lo.w));
        hi.x = __uint_as_float(tf32r(hi.x)); hi.y = __uint_as_float(tf32r(hi.y));
        hi.z = __uint_as_float(tf32r(hi.z)); hi.w = __uint_as_float(tf32r(hi.w));
        float* dst = xscratch + g * 8;
        *(float4*)dst = lo;
        *(float4*)(dst + 4) = hi;
    }
}

// ------------------------------ fused kernel -------------------------------
__global__ void __launch_bounds__(256, 1)
fused_kernel(const float* __restrict__ x,
             const float* __restrict__ bt, const float* __restrict__ bs,
             const float* __restrict__ br, const float* __restrict__ bk,
             float* __restrict__ out) {
    extern __shared__ float sm[];
    uint32_t sb = smaddr(sm);
    int tid = threadIdx.x, wid = tid >> 5, lid = tid & 31;
    int r0 = lid >> 2, c0 = lid & 3;
    int rx3 = r0 & 3;
    int tile = blockIdx.x;
    long g0 = (long)tile * 128;
    bool head = (tile & 127) == 0;          // first tile in a batch row

    int mw = wid >> 2, nw = wid & 3;        // 2M x 4N (gate / out0)
    int mw2 = wid >> 1, nw2 = wid & 1;      // 4M x 2N (out1)

    // ldmatrix lane constants
    int mrow = ((lid >> 3) & 1) * 8 + (lid & 7);   // row within 16-row fragment
    int gh   = lid >> 4;                            // k-half
    int swl  = lid & 7;                             // row&7 for swizzle

    float acc[4][8][4];                             // 128 regs (gate/out0)

    // per-thread loader constants
    const int ldb = tid & 7, ldrow = tid >> 3;      // ldrow 0..31
    const uint32_t ldswzA = (uint32_t)(ldb ^ (ldrow & 7));
    const uint32_t ldswzB = (uint32_t)(ldb ^ ((ldrow & 3) << 1));

    // ---- unified chunk loader: ci = 0..31, pass=ci>>3, kc=ci&7, st=ci%3 ----
    auto loadChunk = [&](int ci) {
        if (ci >= 32) return;
        int pass = ci >> 3, kc = ci & 7, st = ci % 3;
        if (pass < 2) {
            // A chunk (x tile, tap handled here): into m cols 128+st*32
#pragma unroll
            for (int i = 0; i < 4; ++i) {
                int row = ldrow + i * 32;
                const float* srcA = xscratch;
                int sz = 16;
                if (kc < 4) {
                    if (head && row < 4) sz = 0;
                    else srcA = xscratch + (g0 + row - 4) * 128 + kc * 32 + ldb * 4;
                } else {
                    srcA = xscratch + (g0 + row) * 128 + (kc - 4) * 32 + ldb * 4;
                }
                cpa16(sb + (uint32_t)(MOFF + row * 256 + 128 + st * 32 + ldswzA * 4) * 4,
                      srcA, sz);
            }
            // B chunk: 256 rows
            const float* wb = wscratch + pass * 65536;
#pragma unroll
            for (int i = 0; i < 8; ++i) {
                int row = ldrow + i * 32;
                cpa16(sb + (uint32_t)(BOFF + st * 8192 + row * 32 + ldswzB * 4) * 4,
                      wb + row * 256 + kc * 32 + ldb * 4, 16);
            }
        } else if (pass == 2) {
            const float* wb = wscratch + 512 * 256;
#pragma unroll
            for (int i = 0; i < 8; ++i) {
                int row = ldrow + i * 32;
                cpa16(sb + (uint32_t)(BOFF + st * 8192 + row * 32 + ldswzB * 4) * 4,
                      wb + row * 256 + kc * 32 + ldb * 4, 16);
            }
        } else {
            const float* wb = wscratch + 768 * 256;
#pragma unroll
            for (int i = 0; i < 4; ++i) {
                int row = ldrow + i * 32;
                cpa16(sb + (uint32_t)(BOFF + st * 8192 + row * 32 + ldswzB * 4) * 4,
                      wb + row * 256 + kc * 32 + ldb * 4, 16);
            }
        }
    };

    auto zacc = [&]() {
#pragma unroll
        for (int i = 0; i < 4; ++i)
#pragma unroll
            for (int j = 0; j < 8; ++j)
#pragma unroll
                for (int q = 0; q < 4; ++q) acc[i][j][q] = 0.f;
    };

    // ---- gate compute: A from m-region stage (row stride 256, col 128+st*32) ----
    auto gate_compute = [&](int st) {
        uint32_t Abase = sb + (uint32_t)(MOFF + (mw * 64 + mrow) * 256 + 128 + st * 32) * 4;
        const float* Bs = sm + BOFF + st * 8192 + nw * 2048 + r0 * 32;
#pragma unroll
        for (int ks = 0; ks < 4; ++ks) {
            uint32_t xorw = (uint32_t)(((ks << 1) + gh) ^ swl) * 16;
            uint32_t a[4][4];
#pragma unroll
            for (int mf = 0; mf < 4; ++mf)
                ldsm4(a[mf], Abase + mf * 16384 + xorw);
            int o = ((ks ^ rx3) << 3) + 2 * c0;
#pragma unroll
            for (int nf = 0; nf < 8; ++nf) {
                float2 bv = *(const float2*)(Bs + nf * 256 + o);
                uint32_t b[2] = {__float_as_uint(bv.x), __float_as_uint(bv.y)};
#pragma unroll
                for (int mf = 0; mf < 4; ++mf) mma8(acc[mf][nf], a[mf], b);
            }
        }
    };
    // ---- out compute, 256 N rows ----
    auto out_compute256 = [&](int kc, int st) {
        uint32_t Abase = sb + (uint32_t)(MOFF + (mw * 64 + mrow) * 256 + kc * 32) * 4;
        const float* Bs = sm + BOFF + st * 8192 + nw * 2048 + r0 * 32;
#pragma unroll
        for (int ks = 0; ks < 4; ++ks) {
            uint32_t xorw = (uint32_t)(((ks << 1) + gh) ^ swl) * 16;
            uint32_t a[4][4];
#pragma unroll
            for (int mf = 0; mf < 4; ++mf)
                ldsm4(a[mf], Abase + mf * 16384 + xorw);
            int o = ((ks ^ rx3) << 3) + 2 * c0;
#pragma unroll
            for (int nf = 0; nf < 8; ++nf) {
                float2 bv = *(const float2*)(Bs + nf * 256 + o);
                uint32_t b[2] = {__float_as_uint(bv.x), __float_as_uint(bv.y)};
#pragma unroll
                for (int mf = 0; mf < 4; ++mf) mma8(acc[mf][nf], a[mf], b);
            }
        }
    };
    // ---- out compute, 128 N rows: 4M x 2N, warp tile 32x64 ----
    auto out_compute128 = [&](int kc, int st) {
        uint32_t Abase = sb + (uint32_t)(MOFF + (mw2 * 32 + mrow) * 256 + kc * 32) * 4;
        const float* Bs = sm + BOFF + st * 8192 + nw2 * 2048 + r0 * 32;
#pragma unroll
        for (int ks = 0; ks < 4; ++ks) {
            uint32_t xorw = (uint32_t)(((ks << 1) + gh) ^ swl) * 16;
            uint32_t a[2][4];
#pragma unroll
            for (int mf = 0; mf < 2; ++mf)
                ldsm4(a[mf], Abase + mf * 16384 + xorw);
            int o = ((ks ^ rx3) << 3) + 2 * c0;
#pragma unroll
            for (int nf = 0; nf < 8; ++nf) {
                float2 bv = *(const float2*)(Bs + nf * 256 + o);
                uint32_t b[2] = {__float_as_uint(bv.x), __float_as_uint(bv.y)};
#pragma unroll
                for (int mf = 0; mf < 2; ++mf) mma8(acc[mf][nf], a[mf], b);
            }
        }
    };

    // ---- gate epilogue: plain m stores (conflict-free STS.32) ----
    // nf pairs: gs = nf>>1 (0..3), G = nw*4 + gs; thread holds channels
    // (G*8+c0, G*8+c0+4) for rows (rA, rA+8).
    auto gate_epi = [&](int p) {
#pragma unroll
        for (int mf = 0; mf < 4; ++mf) {
            int rA = mw * 64 + mf * 16 + r0;
            float* m0 = sm + MOFF + rA * 256;
            float* m1 = m0 + 8 * 256;
#pragma unroll
            for (int gs = 0; gs < 4; ++gs) {
                int G = nw * 4 + gs;
                int Cb = p * 128 + G * 8;
                float bt0 = __ldg(bt + Cb + c0), bt1 = __ldg(bt + Cb + c0 + 4);
                float bs0 = __ldg(bs + Cb + c0), bs1 = __ldg(bs + Cb + c0 + 4);
                float* At = acc[mf][2 * gs];
                float* Ag = acc[mf][2 * gs + 1];
                int kcblk = p * 4 + (G >> 2);
                int bb = (G & 3) * 2;
                int o0 = kcblk * 32 + ((bb)     ^ r0) * 4 + c0;
                int o1 = kcblk * 32 + ((bb + 1) ^ r0) * 4 + c0;
                m0[o0] = gatem(At[0] + bt0, Ag[0] + bs0);
                m0[o1] = gatem(At[1] + bt1, Ag[1] + bs1);
                m1[o0] = gatem(At[2] + bt0, Ag[2] + bs0);
                m1[o1] = gatem(At[3] + bt1, Ag[3] + bs1);
            }
        }
    };

    float* outR = out;                                // res  [131072,128]
    float* outK = out + (size_t)131072 * 128;         // skip [131072,256]

    // ================= prologue =================
    zacc();
    loadChunk(0); cpcommit();
    loadChunk(1); cpcommit();

    // ================= gate pass 0 (ci 0..7) =================
#pragma unroll 1
    for (int ci = 0; ci < 8; ++ci) {
        CPWAIT(1); __syncthreads();
        gate_compute(ci % 3);
        loadChunk(ci + 2); cpcommit();
    }
    gate_epi(0);        // writes m cols 0..127; disjoint from A stages & B
    zacc();

    // ================= gate pass 1 (ci 8..15) =================
#pragma unroll 1
    for (int ci = 8; ci < 16; ++ci) {
        CPWAIT(1); __syncthreads();
        gate_compute(ci % 3);
        loadChunk(ci + 2); cpcommit();
    }
    __syncthreads();    // all warps done reading A stages (m cols 128..255)
    gate_epi(1);        // overwrite with m cols 128..255
    zacc();

    // ================= out pass 0 (ci 16..23): res | skip 0..127 ==========
#pragma unroll 1
    for (int ci = 16; ci < 24; ++ci) {
        CPWAIT(1); __syncthreads();   // first iter publishes gate_epi(1)
        out_compute256(ci & 7, ci % 3);
        loadChunk(ci + 2); cpcommit();
    }
    {
#pragma unroll
        for (int mf = 0; mf < 4; ++mf) {
            long row0 = g0 + mw * 64 + mf * 16 + r0, row1 = row0 + 8;
#pragma unroll
            for (int nf = 0; nf < 8; ++nf) {
                int pcol = nw * 64 + nf * 8 + 2 * c0;
                float* A = acc[mf][nf];
                if (pcol < 128) {
                    float b0 = __ldg(br + pcol), b1 = __ldg(br + pcol + 1);
                    float2 x0v = *(const float2*)(x + row0 * 128 + pcol);
                    float2 x1v = *(const float2*)(x + row1 * 128 + pcol);
                    *(float2*)(outR + row0 * 128 + pcol) =
                        make_float2(A[0] + b0 + x0v.x, A[1] + b1 + x0v.y);
                    *(float2*)(outR + row1 * 128 + pcol) =
                        make_float2(A[2] + b0 + x1v.x, A[3] + b1 + x1v.y);
                } else {
                    int ck = pcol - 128;
                    float b0 = __ldg(bk + ck), b1 = __ldg(bk + ck + 1);
                    *(float2*)(outK + row0 * 256 + ck) = make_float2(A[0] + b0, A[1] + b1);
                    *(float2*)(outK + row1 * 256 + ck) = make_float2(A[2] + b0, A[3] + b1);
                }
            }
        }
    }
    zacc();

    // ================= out pass 1 (ci 24..31): skip 128..255 =============
#pragma unroll 1
    for (int ci = 24; ci < 32; ++ci) {
        CPWAIT(1); __syncthreads();
        out_compute128(ci & 7, ci % 3);
        loadChunk(ci + 2); cpcommit();
    }
    {
#pragma unroll
        for (int mf = 0; mf < 2; ++mf) {
            long row0 = g0 + mw2 * 32 + mf * 16 + r0, row1 = row0 + 8;
#pragma unroll
            for (int nf = 0; nf < 8; ++nf) {
                int ck = 128 + nw2 * 64 + nf * 8 + 2 * c0;
                float* A = acc[mf][nf];
                float b0 = __ldg(bk + ck), b1 = __ldg(bk + ck + 1);
                *(float2*)(outK + row0 * 256 + ck) = make_float2(A[0] + b0, A[1] + b1);
                *(float2*)(outK + row1 * 256 + ck) = make_float2(A[2] + b0, A[3] + b1);
            }
        }
    }
}

// ------------------------------- launch ------------------------------------
extern "C" void kernel_launch(void* const* d_in, const int* in_sizes, int n_in,
                              void* d_out, int out_size) {
    const float* x  = (const float*)d_in[0];
    const float* wt = (const float*)d_in[1];
    const float* bt = (const float*)d_in[2];
    const float* ws = (const float*)d_in[3];
    const float* bs = (const float*)d_in[4];
    const float* wr = (const float*)d_in[5];
    const float* br = (const float*)d_in[6];
    const float* wk = (const float*)d_in[7];
    const float* bk = (const float*)d_in[8];
    float* out = (float*)d_out;

    cudaFuncSetAttribute(fused_kernel,
                         cudaFuncAttributeMaxDynamicSharedMemorySize, SMEM_BYTES);

    prep_kernel<<<896 + 8192, 256>>>(wt, ws, wr, wk, x);
    fused_kernel<<<1024, 256, SMEM_BYTES>>>(x, bt, bs, br, bk, out);
}

// round 14
// speedup vs baseline: 1.2110x; 1.0458x over previous
#include <cuda_runtime.h>
#include <cstdint>
#include <cstddef>

// ---------------------------------------------------------------------------
// WaveNet gated residual block, tf32 mma.sync (sm_103 baseline PTX).
//
// R13 = R12 resubmitted (R12 never ran: GB300 container infra failure).
//
// Two GEMM kernels at occupancy 2 (fused design is RF-limited to occ 1):
//   gate_kernel: tiles M128 x N128 (interleaved tanh|sig rows -> 64 channels),
//                epilogue m = tanh*sig -> gmem mscratch at PLAIN channel
//                positions (A-side ldmatrix contract: A plain-k, B q-packed-k).
//   out_kernel : tiles M128 x N128 over [res | skip0 | skip1], A = mscratch.
// Both: 8 warps, warp tile 64x32 (acc 64/thread -> 128-reg budget of occ 2),
// ldmatrix A-fragments, LDS.64 q-packed B-fragments, 3-stage cp.async ring,
// one __syncthreads per k32 chunk.
// ---------------------------------------------------------------------------

#define DEVFN __device__ __forceinline__

// smem float offsets (per kernel): A stages 3x4096, B stages 3x4096
static constexpr int AOFF = 0;
static constexpr int BOFF = 12288;
static constexpr int SMEM_BYTES = 24576 * 4;   // 98304 -> 2 CTAs/SM

__device__ float wscratch[896 * 256];        // packed tf32 weights (896 KB)
__device__ float xscratch[131072 * 128];     // tf32-rounded plain x (64 MB)
__device__ float mscratch[(size_t)131072 * 256];  // gated activations m (128 MB)

// ------------------------------- helpers -----------------------------------
DEVFN uint32_t smaddr(const void* p) {
    uint32_t a;
    asm("{ .reg .u64 t; cvta.to.shared.u64 t, %1; cvt.u32.u64 %0, t; }" : "=r"(a) : "l"(p));
    return a;
}
DEVFN uint32_t tf32r(float x) { uint32_t u; asm("cvt.rna.tf32.f32 %0, %1;" : "=r"(u) : "f"(x)); return u; }
DEVFN float ex2f(float x) { float y; asm("ex2.approx.ftz.f32 %0, %1;" : "=f"(y) : "f"(x)); return y; }
DEVFN float rcpf(float x) { float y; asm("rcp.approx.ftz.f32 %0, %1;" : "=f"(y) : "f"(x)); return y; }

// tanh(a)*sigmoid(b) = (u-1)*v/((u+1)(v+1)), u=e^{2a}, v=e^{b}; clamped.
DEVFN float gatem(float a, float b) {
    a = fminf(fmaxf(a, -15.f), 15.f);
    b = fminf(fmaxf(b, -30.f), 30.f);
    float u = ex2f(a * 2.8853900817779268f);
    float v = ex2f(b * 1.4426950408889634f);
    float m = (u - 1.f) * v * rcpf((u + 1.f) * (v + 1.f));
    return __uint_as_float(tf32r(m));
}

DEVFN void cpa16(uint32_t dst, const void* src, int sz) {
    asm volatile("cp.async.cg.shared.global [%0], [%1], 16, %2;"
                 :: "r"(dst), "l"(src), "r"(sz) : "memory");
}
DEVFN void cpcommit() { asm volatile("cp.async.commit_group;" ::: "memory"); }
#define CPWAIT(n) asm volatile("cp.async.wait_group %0;" :: "n"(n) : "memory")

// m16n8k8 tf32 mma, row.col, f32 accum
DEVFN void mma8(float* d, const uint32_t* a, const uint32_t* b) {
    asm("mma.sync.aligned.m16n8k8.row.col.f32.tf32.tf32.f32 "
        "{%0,%1,%2,%3}, {%4,%5,%6,%7}, {%8,%9}, {%0,%1,%2,%3};"
        : "+f"(d[0]), "+f"(d[1]), "+f"(d[2]), "+f"(d[3])
        : "r"(a[0]), "r"(a[1]), "r"(a[2]), "r"(a[3]), "r"(b[0]), "r"(b[1]));
}

// ldmatrix x4: one full 16x8 tf32 A-fragment (b16 view, reg = one tf32)
DEVFN void ldsm4(uint32_t* r, uint32_t addr) {
    asm volatile("ldmatrix.sync.aligned.m8n8.x4.shared.b16 {%0,%1,%2,%3}, [%4];"
                 : "=r"(r[0]), "=r"(r[1]), "=r"(r[2]), "=r"(r[3]) : "r"(addr));
}

// ------------------------------ prep kernel --------------------------------
// wscratch rows (256 q-packed floats each, q(k)=(k&~7)+((k&3)<<1)+((k>>2)&1)):
//   0..511   gate: row = p*256 + t; G=t>>4, is_sig=(t>>3)&1, e=t&7,
//            channel C = p*128 + G*8 + (e>>1) + (e&1)*4  (pairing permutation)
//   512..767 out: res 0..127 | skip 0..127
//   768..895 out: skip 128..255
// xscratch: 128 PLAIN tf32 floats per token.
__global__ void __launch_bounds__(256)
prep_kernel(const float* __restrict__ wt, const float* __restrict__ ws,
            const float* __restrict__ wr, const float* __restrict__ wk,
            const float* __restrict__ x) {
    int bid = blockIdx.x, tid = threadIdx.x;
    if (bid < 896) {
        int idx = bid * 256 + tid;
        int row = idx >> 8, k = idx & 255;
        float v;
        if (row < 512) {
            int p = row >> 8, t = row & 255;
            int G = t >> 4, is_sig = (t >> 3) & 1, e = t & 7;
            int C = p * 128 + G * 8 + (e >> 1) + (e & 1) * 4;
            int src = ((k >> 7) * 128 + (k & 127)) * 256 + C;
            v = is_sig ? ws[src] : wt[src];
        } else if (row < 768) {
            int j = row - 512;
            v = (j < 128) ? wr[k * 128 + j] : wk[k * 256 + (j - 128)];
        } else {
            v = wk[k * 256 + 128 + (row - 768)];
        }
        int q = (k & ~7) + ((k & 3) << 1) + ((k >> 2) & 1);
        wscratch[row * 256 + q] = __uint_as_float(tf32r(v));
    } else {
        size_t g = (size_t)(bid - 896) * 256 + tid;   // < 2097152 groups of 8
        const float* src = x + g * 8;
        float4 lo = *(const float4*)src;
        float4 hi = *(const float4*)(src + 4);
        lo.x = __uint_as_float(tf32r(lo.x)); lo.y = __uint_as_float(tf32r(lo.y));
        lo.z = __uint_as_float(tf32r(lo.z)); lo.w = __uint_as_float(tf32r(lo.w));
        hi.x = __uint_as_float(tf32r(hi.x)); hi.y = __uint_as_float(tf32r(hi.y));
        hi.z = __uint_as_float(tf32r(hi.z)); hi.w = __uint_as_float(tf32r(hi.w));
        float* dst = xscratch + g * 8;
        *(float4*)dst = lo;
        *(float4*)(dst + 4) = hi;
    }
}

// ------------------------------ gate kernel --------------------------------
// grid 4096: ng = bid>>10 (0..3: 128 interleaved gate rows = 64 channels),
//            mt = bid&1023 (128-token tile).
__global__ void __launch_bounds__(256, 2)
gate_kernel(const float* __restrict__ bt, const float* __restrict__ bs) {
    extern __shared__ float sm[];
    uint32_t sb = smaddr(sm);
    int tid = threadIdx.x, wid = tid >> 5, lid = tid & 31;
    int r0 = lid >> 2, c0 = lid & 3;
    int rx3 = r0 & 3;
    int ng = blockIdx.x >> 10;
    int mt = blockIdx.x & 1023;
    long g0 = (long)mt * 128;
    bool head = (mt & 127) == 0;            // first tile in a batch row

    int mw = wid >> 2, nw = wid & 3;        // 2M x 4N, warp 64x32

    int mrow = ((lid >> 3) & 1) * 8 + (lid & 7);
    int gh   = lid >> 4;
    int swl  = lid & 7;

    float acc[4][4][4];
#pragma unroll
    for (int i = 0; i < 4; ++i)
#pragma unroll
        for (int j = 0; j < 4; ++j)
#pragma unroll
            for (int q = 0; q < 4; ++q) acc[i][j][q] = 0.f;

    const int ldb = tid & 7, ldrow = tid >> 3;          // ldrow 0..31
    const uint32_t ldswzA = (uint32_t)(ldb ^ (ldrow & 7));
    const uint32_t ldswzB = (uint32_t)(ldb ^ ((ldrow & 3) << 1));
    const float* wb = wscratch + ng * 32768;

    auto loadChunk = [&](int kc) {
        if (kc >= 8) return;
        int st = kc % 3;
#pragma unroll
        for (int i = 0; i < 4; ++i) {       // A: 128 rows x 32 (tap folded)
            int row = ldrow + i * 32;
            const float* srcA = xscratch;
            int sz = 16;
            if (kc < 4) {
                if (head && row < 4) sz = 0;
                else srcA = xscratch + (g0 + row - 4) * 128 + kc * 32 + ldb * 4;
            } else {
                srcA = xscratch + (g0 + row) * 128 + (kc - 4) * 32 + ldb * 4;
            }
            cpa16(sb + (uint32_t)(AOFF + st * 4096 + row * 32 + ldswzA * 4) * 4, srcA, sz);
        }
#pragma unroll
        for (int i = 0; i < 4; ++i) {       // B: 128 rows x 32
            int row = ldrow + i * 32;
            cpa16(sb + (uint32_t)(BOFF + st * 4096 + row * 32 + ldswzB * 4) * 4,
                  wb + row * 256 + kc * 32 + ldb * 4, 16);
        }
    };

    auto compute = [&](int st) {
        uint32_t Abase = sb + (uint32_t)(AOFF + st * 4096 + (mw * 64 + mrow) * 32) * 4;
        const float* Bs = sm + BOFF + st * 4096 + nw * 1024 + r0 * 32;
#pragma unroll
        for (int ks = 0; ks < 4; ++ks) {
            uint32_t xorw = (uint32_t)(((ks << 1) + gh) ^ swl) * 16;
            uint32_t a[4][4];
#pragma unroll
            for (int mf = 0; mf < 4; ++mf)
                ldsm4(a[mf], Abase + mf * 2048 + xorw);
            int o = ((ks ^ rx3) << 3) + 2 * c0;
#pragma unroll
            for (int nf = 0; nf < 4; ++nf) {
                float2 bv = *(const float2*)(Bs + nf * 256 + o);
                uint32_t b[2] = {__float_as_uint(bv.x), __float_as_uint(bv.y)};
#pragma unroll
                for (int mf = 0; mf < 4; ++mf) mma8(acc[mf][nf], a[mf], b);
            }
        }
    };

    loadChunk(0); cpcommit();
    loadChunk(1); cpcommit();
#pragma unroll 1
    for (int ci = 0; ci < 8; ++ci) {
        CPWAIT(1); __syncthreads();
        compute(ci % 3);
        loadChunk(ci + 2); cpcommit();
    }

    // epilogue: m -> gmem mscratch, PLAIN channel positions (A-side contract).
    // Thread holds channels (Cb+c0, Cb+c0+4) for token rows (tok0, tok1).
#pragma unroll
    for (int mf = 0; mf < 4; ++mf) {
        long tok0 = g0 + mw * 64 + mf * 16 + r0, tok1 = tok0 + 8;
#pragma unroll
        for (int gs = 0; gs < 2; ++gs) {
            int Gl = nw * 2 + gs;
            int Cb = ng * 64 + Gl * 8;
            float bt0 = __ldg(bt + Cb + c0), bt1 = __ldg(bt + Cb + c0 + 4);
            float bs0 = __ldg(bs + Cb + c0), bs1 = __ldg(bs + Cb + c0 + 4);
            float* At = acc[mf][2 * gs];
            float* Ag = acc[mf][2 * gs + 1];
            int Cq = Cb + c0;
            mscratch[tok0 * 256 + Cq]     = gatem(At[0] + bt0, Ag[0] + bs0);
            mscratch[tok0 * 256 + Cq + 4] = gatem(At[1] + bt1, Ag[1] + bs1);
            mscratch[tok1 * 256 + Cq]     = gatem(At[2] + bt0, Ag[2] + bs0);
            mscratch[tok1 * 256 + Cq + 4] = gatem(At[3] + bt1, Ag[3] + bs1);
        }
    }
}

// ------------------------------ out kernel ---------------------------------
// grid 3072: ng = bid>>10 (0: res, 1: skip0..127, 2: skip128..255),
//            mt = bid&1023.
__global__ void __launch_bounds__(256, 2)
out_kernel(const float* __restrict__ x,
           const float* __restrict__ br, const float* __restrict__ bk,
           float* __restrict__ out) {
    extern __shared__ float sm[];
    uint32_t sb = smaddr(sm);
    int tid = threadIdx.x, wid = tid >> 5, lid = tid & 31;
    int r0 = lid >> 2, c0 = lid & 3;
    int rx3 = r0 & 3;
    int ng = blockIdx.x >> 10;
    int mt = blockIdx.x & 1023;
    long g0 = (long)mt * 128;

    int mw = wid >> 2, nw = wid & 3;        // 2M x 4N, warp 64x32

    int mrow = ((lid >> 3) & 1) * 8 + (lid & 7);
    int gh   = lid >> 4;
    int swl  = lid & 7;

    float acc[4][4][4];
#pragma unroll
    for (int i = 0; i < 4; ++i)
#pragma unroll
        for (int j = 0; j < 4; ++j)
#pragma unroll
            for (int q = 0; q < 4; ++q) acc[i][j][q] = 0.f;

    const int ldb = tid & 7, ldrow = tid >> 3;
    const uint32_t ldswzA = (uint32_t)(ldb ^ (ldrow & 7));
    const uint32_t ldswzB = (uint32_t)(ldb ^ ((ldrow & 3) << 1));
    const float* wb = wscratch + (size_t)(512 + ng * 128) * 256;

    auto loadChunk = [&](int kc) {
        if (kc >= 8) return;
        int st = kc % 3;
#pragma unroll
        for (int i = 0; i < 4; ++i) {       // A = m: 128 rows x 32 (plain)
            int row = ldrow + i * 32;
            cpa16(sb + (uint32_t)(AOFF + st * 4096 + row * 32 + ldswzA * 4) * 4,
                  mscratch + (g0 + row) * 256 + kc * 32 + ldb * 4, 16);
        }
#pragma unroll
        for (int i = 0; i < 4; ++i) {       // B: 128 rows x 32 (q-packed)
            int row = ldrow + i * 32;
            cpa16(sb + (uint32_t)(BOFF + st * 4096 + row * 32 + ldswzB * 4) * 4,
                  wb + row * 256 + kc * 32 + ldb * 4, 16);
        }
    };

    auto compute = [&](int st) {
        uint32_t Abase = sb + (uint32_t)(AOFF + st * 4096 + (mw * 64 + mrow) * 32) * 4;
        const float* Bs = sm + BOFF + st * 4096 + nw * 1024 + r0 * 32;
#pragma unroll
        for (int ks = 0; ks < 4; ++ks) {
            uint32_t xorw = (uint32_t)(((ks << 1) + gh) ^ swl) * 16;
            uint32_t a[4][4];
#pragma unroll
            for (int mf = 0; mf < 4; ++mf)
                ldsm4(a[mf], Abase + mf * 2048 + xorw);
            int o = ((ks ^ rx3) << 3) + 2 * c0;
#pragma unroll
            for (int nf = 0; nf < 4; ++nf) {
                float2 bv = *(const float2*)(Bs + nf * 256 + o);
                uint32_t b[2] = {__float_as_uint(bv.x), __float_as_uint(bv.y)};
#pragma unroll
                for (int mf = 0; mf < 4; ++mf) mma8(acc[mf][nf], a[mf], b);
            }
        }
    };

    loadChunk(0); cpcommit();
    loadChunk(1); cpcommit();
#pragma unroll 1
    for (int ci = 0; ci < 8; ++ci) {
        CPWAIT(1); __syncthreads();
        compute(ci % 3);
        loadChunk(ci + 2); cpcommit();
    }

    float* outR = out;                                // res  [131072,128]
    float* outK = out + (size_t)131072 * 128;         // skip [131072,256]
#pragma unroll
    for (int mf = 0; mf < 4; ++mf) {
        long row0 = g0 + mw * 64 + mf * 16 + r0, row1 = row0 + 8;
#pragma unroll
        for (int nf = 0; nf < 4; ++nf) {
            int pcolL = nw * 32 + nf * 8 + 2 * c0;
            float* A = acc[mf][nf];
            if (ng == 0) {
                float b0 = __ldg(br + pcolL), b1 = __ldg(br + pcolL + 1);
                float2 x0v = *(const float2*)(x + row0 * 128 + pcolL);
                float2 x1v = *(const float2*)(x + row1 * 128 + pcolL);
                *(float2*)(outR + row0 * 128 + pcolL) =
                    make_float2(A[0] + b0 + x0v.x, A[1] + b1 + x0v.y);
                *(float2*)(outR + row1 * 128 + pcolL) =
                    make_float2(A[2] + b0 + x1v.x, A[3] + b1 + x1v.y);
            } else {
                int ck = (ng - 1) * 128 + pcolL;
                float b0 = __ldg(bk + ck), b1 = __ldg(bk + ck + 1);
                *(float2*)(outK + row0 * 256 + ck) = make_float2(A[0] + b0, A[1] + b1);
                *(float2*)(outK + row1 * 256 + ck) = make_float2(A[2] + b0, A[3] + b1);
            }
        }
    }
}

// ------------------------------- launch ------------------------------------
extern "C" void kernel_launch(void* const* d_in, const int* in_sizes, int n_in,
                              void* d_out, int out_size) {
    const float* x  = (const float*)d_in[0];
    const float* wt = (const float*)d_in[1];
    const float* bt = (const float*)d_in[2];
    const float* ws = (const float*)d_in[3];
    const float* bs = (const float*)d_in[4];
    const float* wr = (const float*)d_in[5];
    const float* br = (const float*)d_in[6];
    const float* wk = (const float*)d_in[7];
    const float* bk = (const float*)d_in[8];
    float* out = (float*)d_out;

    cudaFuncSetAttribute(gate_kernel,
                         cudaFuncAttributeMaxDynamicSharedMemorySize, SMEM_BYTES);
    cudaFuncSetAttribute(out_kernel,
                         cudaFuncAttributeMaxDynamicSharedMemorySize, SMEM_BYTES);

    prep_kernel<<<896 + 8192, 256>>>(wt, ws, wr, wk, x);
    gate_kernel<<<4096, 256, SMEM_BYTES>>>(bt, bs);
    out_kernel<<<3072, 256, SMEM_BYTES>>>(x, br, bk, out);
}